// round 15
// baseline (speedup 1.0000x reference)
#include <cuda_runtime.h>
#include <cuda_bf16.h>
#include <mma.h>
#include <cstdint>

using namespace nvcuda;

// SigNet: depth-4 path signature (C=8 incl. time) + linear head.
// K1: R10-exact scan; epilogue emits y as split-bf16 (hi+lo).
// K2a: W split-bf16 prep.
// K2b: wmma bf16 GEMM (yh*Wh + yh*Wl + yl*Wh, fp32 acc),
//      grid (4 colg, 2 rowg, 19 ksplit) = 152 CTAs (one wave), K=256/CTA.
// K3: reduce 19 split-k partials + bias, 2-way split-k parallel.

#define NB      128
#define SLEN    1024
#define NSEG    8
#define SEG     128
#define CIN     7
#define SIGCH   4680          // 8 + 64 + 512 + 4096
#define YSTRIDE 4864          // 19*256; pad [4680,4864) stays zero
#define DOUT    256
#define KSPLIT  19
#define KCHUNK  256

__device__ __nv_bfloat16 g_yh[NB * YSTRIDE];
__device__ __nv_bfloat16 g_yl[NB * YSTRIDE];
__device__ __nv_bfloat16 g_wh[DOUT * YSTRIDE];
__device__ __nv_bfloat16 g_wl[DOUT * YSTRIDE];
__device__ float g_part[KSPLIT * NB * DOUT];

// K1 smem: vs[1024][8] = 8192 floats, reused as T[8][4680] = 37440 floats.
#define SMEM_FLOATS (NSEG * SIGCH)     // 149760 B

// ---- Chen combine pieces (X = A o B, A earlier in time) ----
__device__ __forceinline__ void chen_l4(const float* __restrict__ A,
                                        const float* __restrict__ B,
                                        float* __restrict__ X, int lane, int nth)
{
    for (int e = lane; e < 4096; e += nth) {
        float v = A[584 + e] + B[584 + e];
        v = fmaf(A[e >> 9],        B[72 + (e & 511)], v);
        v = fmaf(A[8 + (e >> 6)],  B[8  + (e & 63)],  v);
        v = fmaf(A[72 + (e >> 3)], B[e & 7],          v);
        X[584 + e] = v;
    }
}
__device__ __forceinline__ void chen_l3(const float* __restrict__ A,
                                        const float* __restrict__ B,
                                        float* __restrict__ X, int lane, int nth)
{
    for (int e = lane; e < 512; e += nth) {
        float v = A[72 + e] + B[72 + e];
        v = fmaf(A[e >> 6],       B[8 + (e & 63)], v);
        v = fmaf(A[8 + (e >> 3)], B[e & 7],        v);
        X[72 + e] = v;
    }
}
__device__ __forceinline__ void chen_inplace(float* __restrict__ A,
                                             const float* __restrict__ B,
                                             int lane, int nth)
{
    chen_l4(A, B, A, lane, nth);
    __syncthreads();
    chen_l3(A, B, A, lane, nth);
    float v2 = 0.0f, v1 = 0.0f;
    if (lane < 64) v2 = A[8 + lane] + B[8 + lane] + A[lane >> 3] * B[lane & 7];
    if (lane < 8)  v1 = A[lane] + B[lane];
    __syncthreads();
    if (lane < 64) A[8 + lane] = v2;
    if (lane < 8)  A[lane] = v1;
}

// split-bf16 store of the final signature element
__device__ __forceinline__ void store_hl(size_t i, float v)
{
    __nv_bfloat16 h = __float2bfloat16(v);
    g_yh[i] = h;
    g_yl[i] = __float2bfloat16(v - __bfloat162float(h));
}

// ---------------------------------------------------------------------------
// Kernel 1: R10-exact scan + split-bf16 epilogue.
// ---------------------------------------------------------------------------
__global__ __launch_bounds__(512, 1) void sig_scan_kernel(const float* __restrict__ inp)
{
    extern __shared__ float sm[];
    const int b   = blockIdx.x;
    const int tid = threadIdx.x;

    const float dt = 1.0f / 1023.0f;
    const float* x = inp + (size_t)b * SLEN * CIN;
    for (int i = tid; i < SLEN * CIN; i += 512) {
        int t = i / CIN, c = i - t * CIN;
        float cur  = x[i];
        float prev = (t == 0) ? 0.0f : x[i - CIN];
        sm[t * 8 + c + 1] = cur - prev;
    }
    for (int t = tid; t < SLEN; t += 512)
        sm[t * 8] = (t == 0) ? 0.0f : dt;
    __syncthreads();

    const int g  = tid >> 6;
    const int u  = tid & 63;
    const int a  = u >> 3;
    const int bb = u & 7;

    float s1 = 0.0f, s2 = 0.0f;
    float s3[8];
    float sig4[64];
#pragma unroll
    for (int i = 0; i < 8; i++) s3[i] = 0.0f;
#pragma unroll
    for (int i = 0; i < 64; i++) sig4[i] = 0.0f;

    const float inv24 = 1.0f / 24.0f;
    const float inv6  = 1.0f / 6.0f;
    const float* vrow = sm + g * SEG * 8;

#pragma unroll 1
    for (int t = 0; t < SEG; t++) {
        float vv[8];
        *(float4*)&vv[0] = *(const float4*)&vrow[t * 8];
        *(float4*)&vv[4] = *(const float4*)&vrow[t * 8 + 4];
        float va = vrow[t * 8 + a];
        float vb = vrow[t * 8 + bb];

        float t6 = fmaf(s1, inv6, va * inv24);
        float uu = fmaf(s1, 0.5f, va * inv6);
        float m1 = fmaf(vb, t6, s2 * 0.5f);
        float m2 = fmaf(vb, uu, s2);

        float K[8];
#pragma unroll
        for (int c = 0; c < 8; c++) {
            K[c]  = fmaf(vv[c], m1, s3[c]);
            s3[c] = fmaf(vv[c], m2, s3[c]);
        }
#pragma unroll
        for (int c = 0; c < 8; c++)
#pragma unroll
            for (int d = 0; d < 8; d++)
                sig4[c * 8 + d] = fmaf(K[c], vv[d], sig4[c * 8 + d]);

        s2 = fmaf(vb, fmaf(va, 0.5f, s1), s2);
        s1 += va;
    }

    __syncthreads();

    float* P = sm + g * SIGCH;
#pragma unroll
    for (int c = 0; c < 8; c++) {
#pragma unroll
        for (int d = 0; d < 8; d++)
            P[584 + u * 64 + c * 8 + d] = sig4[c * 8 + d];
        P[72 + u * 8 + c] = s3[c];
    }
    P[8 + u] = s2;
    if (bb == 0) P[a] = s1;
    __syncthreads();

    {
        int pair = tid >> 7, lane = tid & 127;
        float* A = sm + (2 * pair) * SIGCH;
        chen_inplace(A, A + SIGCH, lane, 128);
    }
    __syncthreads();
    {
        int pair = tid >> 8, lane = tid & 255;
        float* A = sm + (4 * pair) * SIGCH;
        chen_inplace(A, A + 2 * SIGCH, lane, 256);
    }
    __syncthreads();
    // Final combine -> split-bf16 straight to global.
    {
        const float* A = sm;
        const float* B = sm + 4 * SIGCH;
        size_t base = (size_t)b * YSTRIDE;
        for (int e = tid; e < 4096; e += 512) {
            float v = A[584 + e] + B[584 + e];
            v = fmaf(A[e >> 9],        B[72 + (e & 511)], v);
            v = fmaf(A[8 + (e >> 6)],  B[8  + (e & 63)],  v);
            v = fmaf(A[72 + (e >> 3)], B[e & 7],          v);
            store_hl(base + 584 + e, v);
        }
        {
            int e = tid;                      // 512 threads cover 512 elems
            float v = A[72 + e] + B[72 + e];
            v = fmaf(A[e >> 6],       B[8 + (e & 63)], v);
            v = fmaf(A[8 + (e >> 3)], B[e & 7],        v);
            store_hl(base + 72 + e, v);
        }
        if (tid < 64) store_hl(base + 8 + tid,
                               A[8 + tid] + B[8 + tid] + A[tid >> 3] * B[tid & 7]);
        if (tid < 8)  store_hl(base + tid, A[tid] + B[tid]);
        if (tid < YSTRIDE - SIGCH) store_hl(base + SIGCH + tid, 0.0f);  // 184 pads
    }
}

// ---------------------------------------------------------------------------
// Kernel 2a: split W into bf16 hi/lo (pad region -> 0).
// ---------------------------------------------------------------------------
__global__ void wprep_kernel(const float* __restrict__ W)
{
    int idx = blockIdx.x * 256 + threadIdx.x;        // 0 .. DOUT*YSTRIDE
    int n = idx / YSTRIDE, k = idx - n * YSTRIDE;
    float v = (k < SIGCH) ? W[n * SIGCH + k] : 0.0f;
    __nv_bfloat16 h = __float2bfloat16(v);
    g_wh[idx] = h;
    g_wl[idx] = __float2bfloat16(v - __bfloat162float(h));
}

// ---------------------------------------------------------------------------
// Kernel 2b: wmma bf16 split GEMM. grid (4 colg, 2 rowg, 19 sp) = 152 CTAs.
// CTA: 64 rows x 64 cols x K=256 (two 128-k sub-chunks reusing the smem
// tiles). 128 threads = 4 warps; warp w owns the 16-row strip, 4 col-frags.
// fp32 accumulate of Ah*Bh + Ah*Bl + Al*Bh. Tiles ld=136 bf16.
// ---------------------------------------------------------------------------
#define LDT 136                            // tile leading dim in bf16
#define T_BYTES (64 * LDT * 2)             // 17408 B per tile
#define MMA_SMEM (4 * T_BYTES)             // 69632 B: Ah, Al, Bh, Bl

__global__ __launch_bounds__(128, 2) void mma_kernel()
{
    extern __shared__ __nv_bfloat16 ts[];
    __nv_bfloat16* sAh = ts;
    __nv_bfloat16* sAl = ts + 64 * LDT;
    __nv_bfloat16* sBh = ts + 2 * 64 * LDT;
    __nv_bfloat16* sBl = ts + 3 * 64 * LDT;

    const int tid  = threadIdx.x;
    const int wid  = tid >> 5;
    const int colg = blockIdx.x;            // cols colg*64 ..
    const int rowg = blockIdx.y;            // rows rowg*64 ..
    const int sp   = blockIdx.z;            // k in [sp*256, sp*256+256)

    wmma::fragment<wmma::accumulator, 16, 16, 16, float> acc[4];
#pragma unroll
    for (int i = 0; i < 4; i++) wmma::fill_fragment(acc[i], 0.0f);

    const uint32_t* yh32 = (const uint32_t*)g_yh;
    const uint32_t* yl32 = (const uint32_t*)g_yl;
    const uint32_t* wh32 = (const uint32_t*)g_wh;
    const uint32_t* wl32 = (const uint32_t*)g_wl;

#pragma unroll 1
    for (int ch = 0; ch < 2; ch++) {
        const int kb = sp * KCHUNK + ch * 128;

        // Load A tiles (64 rows x 128 k, hi+lo): 4096 u32 per tile.
        for (int t = tid; t < 4096; t += 128) {
            int r = t >> 6, j = t & 63;
            uint32_t src = (rowg * 64 + r) * (YSTRIDE / 2) + (kb >> 1) + j;
            ((uint32_t*)(sAh))[r * (LDT / 2) + j] = yh32[src];
            ((uint32_t*)(sAl))[r * (LDT / 2) + j] = yl32[src];
        }
        // Load B tiles (64 cols x 128 k, hi+lo).
        for (int t = tid; t < 4096; t += 128) {
            int n = t >> 6, j = t & 63;
            uint32_t src = (colg * 64 + n) * (YSTRIDE / 2) + (kb >> 1) + j;
            ((uint32_t*)(sBh))[n * (LDT / 2) + j] = wh32[src];
            ((uint32_t*)(sBl))[n * (LDT / 2) + j] = wl32[src];
        }
        __syncthreads();

#pragma unroll
        for (int ks = 0; ks < 8; ks++) {
            wmma::fragment<wmma::matrix_a, 16, 16, 16, __nv_bfloat16, wmma::row_major> ah, al;
            wmma::load_matrix_sync(ah, sAh + (wid * 16) * LDT + ks * 16, LDT);
            wmma::load_matrix_sync(al, sAl + (wid * 16) * LDT + ks * 16, LDT);
#pragma unroll
            for (int cf = 0; cf < 4; cf++) {
                wmma::fragment<wmma::matrix_b, 16, 16, 16, __nv_bfloat16, wmma::col_major> bh, bl;
                wmma::load_matrix_sync(bh, sBh + (cf * 16) * LDT + ks * 16, LDT);
                wmma::load_matrix_sync(bl, sBl + (cf * 16) * LDT + ks * 16, LDT);
                wmma::mma_sync(acc[cf], ah, bh, acc[cf]);
                wmma::mma_sync(acc[cf], ah, bl, acc[cf]);
                wmma::mma_sync(acc[cf], al, bh, acc[cf]);
            }
        }
        __syncthreads();    // tiles reused next sub-chunk
    }

    float* p = g_part + (size_t)sp * NB * DOUT
             + (rowg * 64 + wid * 16) * DOUT + colg * 64;
#pragma unroll
    for (int cf = 0; cf < 4; cf++)
        wmma::store_matrix_sync(p + cf * 16, acc[cf], DOUT, wmma::mem_row_major);
}

// ---------------------------------------------------------------------------
// Kernel 3: reduce 19 partials + bias. 2 threads per output element:
// thread half h sums splits h, h+2, ...; shfl_xor(1) combines.
// grid 256 x 256 = 65536 threads = 32768 outputs.
// ---------------------------------------------------------------------------
__global__ void reduce_bias_kernel(const float* __restrict__ bias, float* __restrict__ out)
{
    int gid  = blockIdx.x * 256 + threadIdx.x;
    int idx  = gid >> 1;                 // output element [b][o]
    int half = gid & 1;
    float v = 0.0f;
#pragma unroll
    for (int s = 0; s < KSPLIT; s += 2) {
        int sp = s + half;
        if (sp < KSPLIT) v += g_part[sp * NB * DOUT + idx];
    }
    v += __shfl_xor_sync(0xFFFFFFFFu, v, 1);
    if (half == 0) out[idx] = v + bias[idx & (DOUT - 1)];
}

// ---------------------------------------------------------------------------
extern "C" void kernel_launch(void* const* d_in, const int* in_sizes, int n_in,
                              void* d_out, int out_size)
{
    (void)in_sizes; (void)n_in; (void)out_size;
    const float* inp  = (const float*)d_in[0];   // (128,1024,7)
    const float* W    = (const float*)d_in[1];   // (256,4680)
    const float* bias = (const float*)d_in[2];   // (256,)
    float* out = (float*)d_out;                  // (128,256)

    const int smem_bytes = SMEM_FLOATS * sizeof(float);   // 149760
    cudaFuncSetAttribute(sig_scan_kernel,
                         cudaFuncAttributeMaxDynamicSharedMemorySize, smem_bytes);
    cudaFuncSetAttribute(mma_kernel,
                         cudaFuncAttributeMaxDynamicSharedMemorySize, MMA_SMEM);

    sig_scan_kernel<<<NB, 512, smem_bytes>>>(inp);
    wprep_kernel<<<(DOUT * YSTRIDE) / 256, 256>>>(W);
    dim3 g2(4, 2, KSPLIT);
    mma_kernel<<<g2, 128, MMA_SMEM>>>();
    reduce_bias_kernel<<<256, 256>>>(bias, out);
}

// round 16
// speedup vs baseline: 1.1439x; 1.1439x over previous
#include <cuda_runtime.h>
#include <cuda_bf16.h>
#include <mma.h>
#include <cstdint>

using namespace nvcuda;

// SigNet: depth-4 path signature (C=8 incl. time) + linear head.
// K1: R10-exact scan (fp32 g_y) + out[b][:] = bias[:] init.
// K2: fused wmma GEMM — stages fp32 y/W tiles with in-kernel bf16 hi/lo split,
//     3-product accumulate (yh*Wh + yh*Wl + yl*Wh) in fp32 fragments,
//     atomicAdd epilogue straight into out. No wprep, no g_part, no reduce.

#define NB      128
#define SLEN    1024
#define NSEG    8
#define SEG     128
#define CIN     7
#define SIGCH   4680          // 8 + 64 + 512 + 4096
#define YSTRIDE 4736          // 37*128; pad [4680,4736) stays zero
#define DOUT    256
#define KSPLIT  37
#define KCHUNK  128

__device__ float g_y[NB * YSTRIDE];

// K1 smem: vs[1024][8] = 8192 floats, reused as T[8][4680] = 37440 floats.
#define SMEM_FLOATS (NSEG * SIGCH)     // 149760 B

// ---- Chen combine pieces (X = A o B, A earlier in time) ----
__device__ __forceinline__ void chen_l4(const float* __restrict__ A,
                                        const float* __restrict__ B,
                                        float* __restrict__ X, int lane, int nth)
{
    for (int e = lane; e < 4096; e += nth) {
        float v = A[584 + e] + B[584 + e];
        v = fmaf(A[e >> 9],        B[72 + (e & 511)], v);
        v = fmaf(A[8 + (e >> 6)],  B[8  + (e & 63)],  v);
        v = fmaf(A[72 + (e >> 3)], B[e & 7],          v);
        X[584 + e] = v;
    }
}
__device__ __forceinline__ void chen_l3(const float* __restrict__ A,
                                        const float* __restrict__ B,
                                        float* __restrict__ X, int lane, int nth)
{
    for (int e = lane; e < 512; e += nth) {
        float v = A[72 + e] + B[72 + e];
        v = fmaf(A[e >> 6],       B[8 + (e & 63)], v);
        v = fmaf(A[8 + (e >> 3)], B[e & 7],        v);
        X[72 + e] = v;
    }
}
__device__ __forceinline__ void chen_inplace(float* __restrict__ A,
                                             const float* __restrict__ B,
                                             int lane, int nth)
{
    chen_l4(A, B, A, lane, nth);
    __syncthreads();
    chen_l3(A, B, A, lane, nth);
    float v2 = 0.0f, v1 = 0.0f;
    if (lane < 64) v2 = A[8 + lane] + B[8 + lane] + A[lane >> 3] * B[lane & 7];
    if (lane < 8)  v1 = A[lane] + B[lane];
    __syncthreads();
    if (lane < 64) A[8 + lane] = v2;
    if (lane < 8)  A[lane] = v1;
}

// ---------------------------------------------------------------------------
// Kernel 1: R10-exact segmented scan + out=bias init.
// ---------------------------------------------------------------------------
__global__ __launch_bounds__(512, 1) void sig_scan_kernel(const float* __restrict__ inp,
                                                          const float* __restrict__ bias,
                                                          float* __restrict__ out)
{
    extern __shared__ float sm[];
    const int b   = blockIdx.x;
    const int tid = threadIdx.x;

    // out[b][:] = bias[:]  (K2 atomically accumulates on top; stream-ordered)
    if (tid < DOUT) out[b * DOUT + tid] = bias[tid];

    const float dt = 1.0f / 1023.0f;
    const float* x = inp + (size_t)b * SLEN * CIN;
    for (int i = tid; i < SLEN * CIN; i += 512) {
        int t = i / CIN, c = i - t * CIN;
        float cur  = x[i];
        float prev = (t == 0) ? 0.0f : x[i - CIN];
        sm[t * 8 + c + 1] = cur - prev;
    }
    for (int t = tid; t < SLEN; t += 512)
        sm[t * 8] = (t == 0) ? 0.0f : dt;
    __syncthreads();

    const int g  = tid >> 6;
    const int u  = tid & 63;
    const int a  = u >> 3;
    const int bb = u & 7;

    float s1 = 0.0f, s2 = 0.0f;
    float s3[8];
    float sig4[64];
#pragma unroll
    for (int i = 0; i < 8; i++) s3[i] = 0.0f;
#pragma unroll
    for (int i = 0; i < 64; i++) sig4[i] = 0.0f;

    const float inv24 = 1.0f / 24.0f;
    const float inv6  = 1.0f / 6.0f;
    const float* vrow = sm + g * SEG * 8;

#pragma unroll 1
    for (int t = 0; t < SEG; t++) {
        float vv[8];
        *(float4*)&vv[0] = *(const float4*)&vrow[t * 8];
        *(float4*)&vv[4] = *(const float4*)&vrow[t * 8 + 4];
        float va = vrow[t * 8 + a];
        float vb = vrow[t * 8 + bb];

        float t6 = fmaf(s1, inv6, va * inv24);
        float uu = fmaf(s1, 0.5f, va * inv6);
        float m1 = fmaf(vb, t6, s2 * 0.5f);
        float m2 = fmaf(vb, uu, s2);

        float K[8];
#pragma unroll
        for (int c = 0; c < 8; c++) {
            K[c]  = fmaf(vv[c], m1, s3[c]);
            s3[c] = fmaf(vv[c], m2, s3[c]);
        }
#pragma unroll
        for (int c = 0; c < 8; c++)
#pragma unroll
            for (int d = 0; d < 8; d++)
                sig4[c * 8 + d] = fmaf(K[c], vv[d], sig4[c * 8 + d]);

        s2 = fmaf(vb, fmaf(va, 0.5f, s1), s2);
        s1 += va;
    }

    __syncthreads();

    float* P = sm + g * SIGCH;
#pragma unroll
    for (int c = 0; c < 8; c++) {
#pragma unroll
        for (int d = 0; d < 8; d++)
            P[584 + u * 64 + c * 8 + d] = sig4[c * 8 + d];
        P[72 + u * 8 + c] = s3[c];
    }
    P[8 + u] = s2;
    if (bb == 0) P[a] = s1;
    __syncthreads();

    {
        int pair = tid >> 7, lane = tid & 127;
        float* A = sm + (2 * pair) * SIGCH;
        chen_inplace(A, A + SIGCH, lane, 128);
    }
    __syncthreads();
    {
        int pair = tid >> 8, lane = tid & 255;
        float* A = sm + (4 * pair) * SIGCH;
        chen_inplace(A, A + 2 * SIGCH, lane, 256);
    }
    __syncthreads();
    {
        const float* A = sm;
        const float* B = sm + 4 * SIGCH;
        float* y = g_y + (size_t)b * YSTRIDE;
        chen_l4(A, B, y, tid, 512);
        chen_l3(A, B, y, tid, 512);
        if (tid < 64) y[8 + tid] = A[8 + tid] + B[8 + tid] + A[tid >> 3] * B[tid & 7];
        if (tid < 8)  y[tid] = A[tid] + B[tid];
        if (tid < YSTRIDE - SIGCH) y[SIGCH + tid] = 0.0f;   // 56 pad elems
    }
}

// ---------------------------------------------------------------------------
// Kernel 2: fused wmma split-bf16 GEMM with atomic epilogue.
// grid (4 colg, 2 rowg, 37 sp) = 296 CTAs, 128 threads = 4 warps.
// CTA: 64 rows x 64 cols x K=128. Tiles staged from fp32 with in-kernel
// hi/lo bf16 split (ld=136). Warp w: 16-row strip, 4 col-fragments.
// Epilogue: fragments -> smem scratch -> atomicAdd into out.
// ---------------------------------------------------------------------------
#define LDT 136                            // tile leading dim in bf16
#define T_ELEMS (64 * LDT)
#define MMA_SMEM (4 * T_ELEMS * 2)         // 69632 B: Ah, Al, Bh, Bl

__global__ __launch_bounds__(128, 2) void mma_kernel(const float* __restrict__ W,
                                                     float* __restrict__ out)
{
    extern __shared__ __nv_bfloat16 ts[];
    __nv_bfloat16* sAh = ts;
    __nv_bfloat16* sAl = ts + T_ELEMS;
    __nv_bfloat16* sBh = ts + 2 * T_ELEMS;
    __nv_bfloat16* sBl = ts + 3 * T_ELEMS;

    const int tid  = threadIdx.x;
    const int wid  = tid >> 5;
    const int colg = blockIdx.x;            // cols colg*64 ..
    const int rowg = blockIdx.y;            // rows rowg*64 ..
    const int sp   = blockIdx.z;            // k in [sp*128, sp*128+128)
    const int kb   = sp * KCHUNK;

    // Stage A: 64 rows x 128 k from fp32 g_y (always in-bounds; pad is zero).
    // 2048 float4 loads; thread handles 16.
    for (int idx = tid; idx < 2048; idx += 128) {
        int r = idx >> 5, j = idx & 31;              // j-th float4 in the row
        float4 v = *(const float4*)&g_y[(size_t)(rowg * 64 + r) * YSTRIDE + kb + j * 4];
        int o = r * LDT + j * 4;
        float e[4] = {v.x, v.y, v.z, v.w};
#pragma unroll
        for (int q = 0; q < 4; q++) {
            __nv_bfloat16 h = __float2bfloat16(e[q]);
            sAh[o + q] = h;
            sAl[o + q] = __float2bfloat16(e[q] - __bfloat162float(h));
        }
    }
    // Stage B: 64 cols x 128 k from fp32 W (row stride SIGCH; guard k>=SIGCH).
    if (kb + KCHUNK <= SIGCH) {
        for (int idx = tid; idx < 2048; idx += 128) {
            int n = idx >> 5, j = idx & 31;
            float4 v = *(const float4*)&W[(size_t)(colg * 64 + n) * SIGCH + kb + j * 4];
            int o = n * LDT + j * 4;
            float e[4] = {v.x, v.y, v.z, v.w};
#pragma unroll
            for (int q = 0; q < 4; q++) {
                __nv_bfloat16 h = __float2bfloat16(e[q]);
                sBh[o + q] = h;
                sBl[o + q] = __float2bfloat16(e[q] - __bfloat162float(h));
            }
        }
    } else {
        for (int idx = tid; idx < 8192; idx += 128) {
            int n = idx >> 7, k = idx & 127;
            int kg = kb + k;
            float v = (kg < SIGCH) ? W[(size_t)(colg * 64 + n) * SIGCH + kg] : 0.0f;
            __nv_bfloat16 h = __float2bfloat16(v);
            sBh[n * LDT + k] = h;
            sBl[n * LDT + k] = __float2bfloat16(v - __bfloat162float(h));
        }
    }
    __syncthreads();

    wmma::fragment<wmma::accumulator, 16, 16, 16, float> acc[4];
#pragma unroll
    for (int i = 0; i < 4; i++) wmma::fill_fragment(acc[i], 0.0f);

#pragma unroll
    for (int ks = 0; ks < 8; ks++) {
        wmma::fragment<wmma::matrix_a, 16, 16, 16, __nv_bfloat16, wmma::row_major> ah, al;
        wmma::load_matrix_sync(ah, sAh + (wid * 16) * LDT + ks * 16, LDT);
        wmma::load_matrix_sync(al, sAl + (wid * 16) * LDT + ks * 16, LDT);
#pragma unroll
        for (int cf = 0; cf < 4; cf++) {
            // B tile is [n][k]; col_major fragment reads element (k, n) at
            // ptr[k + n*LDT] — matches.
            wmma::fragment<wmma::matrix_b, 16, 16, 16, __nv_bfloat16, wmma::col_major> bh, bl;
            wmma::load_matrix_sync(bh, sBh + (cf * 16) * LDT + ks * 16, LDT);
            wmma::load_matrix_sync(bl, sBl + (cf * 16) * LDT + ks * 16, LDT);
            wmma::mma_sync(acc[cf], ah, bh, acc[cf]);
            wmma::mma_sync(acc[cf], ah, bl, acc[cf]);
            wmma::mma_sync(acc[cf], al, bh, acc[cf]);
        }
    }

    // Epilogue: fragments -> smem scratch (tiles dead) -> atomicAdd into out.
    __syncthreads();
    float* sc = (float*)ts;                 // 4 warps x 16 x 64 fp32 = 16 KB
#pragma unroll
    for (int cf = 0; cf < 4; cf++)
        wmma::store_matrix_sync(sc + wid * 1024 + cf * 16, acc[cf], 64,
                                wmma::mem_row_major);
    __syncthreads();

    for (int e = tid; e < 4096; e += 128) {
        int w  = e >> 10;                   // source warp strip
        int rr = (e >> 6) & 15;
        int cc = e & 63;
        int row = rowg * 64 + w * 16 + rr;
        atomicAdd(&out[row * DOUT + colg * 64 + cc], sc[e]);
    }
}

// ---------------------------------------------------------------------------
extern "C" void kernel_launch(void* const* d_in, const int* in_sizes, int n_in,
                              void* d_out, int out_size)
{
    (void)in_sizes; (void)n_in; (void)out_size;
    const float* inp  = (const float*)d_in[0];   // (128,1024,7)
    const float* W    = (const float*)d_in[1];   // (256,4680)
    const float* bias = (const float*)d_in[2];   // (256,)
    float* out = (float*)d_out;                  // (128,256)

    const int smem_bytes = SMEM_FLOATS * sizeof(float);   // 149760
    cudaFuncSetAttribute(sig_scan_kernel,
                         cudaFuncAttributeMaxDynamicSharedMemorySize, smem_bytes);
    cudaFuncSetAttribute(mma_kernel,
                         cudaFuncAttributeMaxDynamicSharedMemorySize, MMA_SMEM);

    sig_scan_kernel<<<NB, 512, smem_bytes>>>(inp, bias, out);
    dim3 g2(4, 2, KSPLIT);
    mma_kernel<<<g2, 128, MMA_SMEM>>>(W, out);
}

// round 17
// speedup vs baseline: 1.2281x; 1.0736x over previous
#include <cuda_runtime.h>
#include <cuda_bf16.h>
#include <mma.h>
#include <cstdint>

using namespace nvcuda;

// SigNet: depth-4 path signature (C=8 incl. time) + linear head.
// K1: R10-exact scan (fp32 g_y) + out[b][:] = bias[:] init.
// K2: fused wmma GEMM — in-kernel bf16 hi/lo split of fp32 y/W tiles,
//     3-product accumulate (yh*Wh + yh*Wl + yl*Wh) in fp32 fragments,
//     atomicAdd epilogue into out. 256 thr / 8 warps, regs capped at 128.

#define NB      128
#define SLEN    1024
#define NSEG    8
#define SEG     128
#define CIN     7
#define SIGCH   4680          // 8 + 64 + 512 + 4096
#define YSTRIDE 4736          // 37*128; pad [4680,4736) stays zero
#define DOUT    256
#define KSPLIT  37
#define KCHUNK  128

__device__ float g_y[NB * YSTRIDE];

// K1 smem: vs[1024][8] = 8192 floats, reused as T[8][4680] = 37440 floats.
#define SMEM_FLOATS (NSEG * SIGCH)     // 149760 B

// ---- Chen combine pieces (X = A o B, A earlier in time) ----
__device__ __forceinline__ void chen_l4(const float* __restrict__ A,
                                        const float* __restrict__ B,
                                        float* __restrict__ X, int lane, int nth)
{
    for (int e = lane; e < 4096; e += nth) {
        float v = A[584 + e] + B[584 + e];
        v = fmaf(A[e >> 9],        B[72 + (e & 511)], v);
        v = fmaf(A[8 + (e >> 6)],  B[8  + (e & 63)],  v);
        v = fmaf(A[72 + (e >> 3)], B[e & 7],          v);
        X[584 + e] = v;
    }
}
__device__ __forceinline__ void chen_l3(const float* __restrict__ A,
                                        const float* __restrict__ B,
                                        float* __restrict__ X, int lane, int nth)
{
    for (int e = lane; e < 512; e += nth) {
        float v = A[72 + e] + B[72 + e];
        v = fmaf(A[e >> 6],       B[8 + (e & 63)], v);
        v = fmaf(A[8 + (e >> 3)], B[e & 7],        v);
        X[72 + e] = v;
    }
}
__device__ __forceinline__ void chen_inplace(float* __restrict__ A,
                                             const float* __restrict__ B,
                                             int lane, int nth)
{
    chen_l4(A, B, A, lane, nth);
    __syncthreads();
    chen_l3(A, B, A, lane, nth);
    float v2 = 0.0f, v1 = 0.0f;
    if (lane < 64) v2 = A[8 + lane] + B[8 + lane] + A[lane >> 3] * B[lane & 7];
    if (lane < 8)  v1 = A[lane] + B[lane];
    __syncthreads();
    if (lane < 64) A[8 + lane] = v2;
    if (lane < 8)  A[lane] = v1;
}

// ---------------------------------------------------------------------------
// Kernel 1: R10-exact segmented scan + out=bias init.
// ---------------------------------------------------------------------------
__global__ __launch_bounds__(512, 1) void sig_scan_kernel(const float* __restrict__ inp,
                                                          const float* __restrict__ bias,
                                                          float* __restrict__ out)
{
    extern __shared__ float sm[];
    const int b   = blockIdx.x;
    const int tid = threadIdx.x;

    // out[b][:] = bias[:]  (K2 atomically accumulates on top; stream-ordered)
    if (tid < DOUT) out[b * DOUT + tid] = bias[tid];

    const float dt = 1.0f / 1023.0f;
    const float* x = inp + (size_t)b * SLEN * CIN;
    for (int i = tid; i < SLEN * CIN; i += 512) {
        int t = i / CIN, c = i - t * CIN;
        float cur  = x[i];
        float prev = (t == 0) ? 0.0f : x[i - CIN];
        sm[t * 8 + c + 1] = cur - prev;
    }
    for (int t = tid; t < SLEN; t += 512)
        sm[t * 8] = (t == 0) ? 0.0f : dt;
    __syncthreads();

    const int g  = tid >> 6;
    const int u  = tid & 63;
    const int a  = u >> 3;
    const int bb = u & 7;

    float s1 = 0.0f, s2 = 0.0f;
    float s3[8];
    float sig4[64];
#pragma unroll
    for (int i = 0; i < 8; i++) s3[i] = 0.0f;
#pragma unroll
    for (int i = 0; i < 64; i++) sig4[i] = 0.0f;

    const float inv24 = 1.0f / 24.0f;
    const float inv6  = 1.0f / 6.0f;
    const float* vrow = sm + g * SEG * 8;

#pragma unroll 1
    for (int t = 0; t < SEG; t++) {
        float vv[8];
        *(float4*)&vv[0] = *(const float4*)&vrow[t * 8];
        *(float4*)&vv[4] = *(const float4*)&vrow[t * 8 + 4];
        float va = vrow[t * 8 + a];
        float vb = vrow[t * 8 + bb];

        float t6 = fmaf(s1, inv6, va * inv24);
        float uu = fmaf(s1, 0.5f, va * inv6);
        float m1 = fmaf(vb, t6, s2 * 0.5f);
        float m2 = fmaf(vb, uu, s2);

        float K[8];
#pragma unroll
        for (int c = 0; c < 8; c++) {
            K[c]  = fmaf(vv[c], m1, s3[c]);
            s3[c] = fmaf(vv[c], m2, s3[c]);
        }
#pragma unroll
        for (int c = 0; c < 8; c++)
#pragma unroll
            for (int d = 0; d < 8; d++)
                sig4[c * 8 + d] = fmaf(K[c], vv[d], sig4[c * 8 + d]);

        s2 = fmaf(vb, fmaf(va, 0.5f, s1), s2);
        s1 += va;
    }

    __syncthreads();

    float* P = sm + g * SIGCH;
#pragma unroll
    for (int c = 0; c < 8; c++) {
#pragma unroll
        for (int d = 0; d < 8; d++)
            P[584 + u * 64 + c * 8 + d] = sig4[c * 8 + d];
        P[72 + u * 8 + c] = s3[c];
    }
    P[8 + u] = s2;
    if (bb == 0) P[a] = s1;
    __syncthreads();

    {
        int pair = tid >> 7, lane = tid & 127;
        float* A = sm + (2 * pair) * SIGCH;
        chen_inplace(A, A + SIGCH, lane, 128);
    }
    __syncthreads();
    {
        int pair = tid >> 8, lane = tid & 255;
        float* A = sm + (4 * pair) * SIGCH;
        chen_inplace(A, A + 2 * SIGCH, lane, 256);
    }
    __syncthreads();
    {
        const float* A = sm;
        const float* B = sm + 4 * SIGCH;
        float* y = g_y + (size_t)b * YSTRIDE;
        chen_l4(A, B, y, tid, 512);
        chen_l3(A, B, y, tid, 512);
        if (tid < 64) y[8 + tid] = A[8 + tid] + B[8 + tid] + A[tid >> 3] * B[tid & 7];
        if (tid < 8)  y[tid] = A[tid] + B[tid];
        if (tid < YSTRIDE - SIGCH) y[SIGCH + tid] = 0.0f;   // 56 pad elems
    }
}

// ---------------------------------------------------------------------------
// Kernel 2: fused wmma split-bf16 GEMM with atomic epilogue.
// grid (4 colg, 2 rowg, 37 sp) = 296 CTAs, 256 threads = 8 warps.
// Warp w: rows (w>>1)*16.., cols (w&1)*32.. -> 2 accum fragments.
// Tiles staged from fp32 with in-kernel hi/lo bf16 split (ld=136).
// ---------------------------------------------------------------------------
#define LDT 136                            // tile leading dim in bf16
#define T_ELEMS (64 * LDT)
#define MMA_SMEM (4 * T_ELEMS * 2)         // 69632 B: Ah, Al, Bh, Bl

__global__ __launch_bounds__(256, 2) void mma_kernel(const float* __restrict__ W,
                                                     float* __restrict__ out)
{
    extern __shared__ __nv_bfloat16 ts[];
    __nv_bfloat16* sAh = ts;
    __nv_bfloat16* sAl = ts + T_ELEMS;
    __nv_bfloat16* sBh = ts + 2 * T_ELEMS;
    __nv_bfloat16* sBl = ts + 3 * T_ELEMS;

    const int tid  = threadIdx.x;
    const int wid  = tid >> 5;
    const int rs   = wid >> 1;              // row strip 0..3 (16 rows each)
    const int chf  = wid & 1;               // col half 0..1 (32 cols each)
    const int colg = blockIdx.x;            // cols colg*64 ..
    const int rowg = blockIdx.y;            // rows rowg*64 ..
    const int sp   = blockIdx.z;            // k in [sp*128, sp*128+128)
    const int kb   = sp * KCHUNK;

    // Stage A: 64 rows x 128 k from fp32 g_y (pad region is zero, in-bounds).
    for (int idx = tid; idx < 2048; idx += 256) {
        int r = idx >> 5, j = idx & 31;              // j-th float4 in the row
        float4 v = *(const float4*)&g_y[(size_t)(rowg * 64 + r) * YSTRIDE + kb + j * 4];
        int o = r * LDT + j * 4;
        float e[4] = {v.x, v.y, v.z, v.w};
#pragma unroll
        for (int q = 0; q < 4; q++) {
            __nv_bfloat16 h = __float2bfloat16(e[q]);
            sAh[o + q] = h;
            sAl[o + q] = __float2bfloat16(e[q] - __bfloat162float(h));
        }
    }
    // Stage B: 64 cols x 128 k from fp32 W (row stride SIGCH; guard tail).
    if (kb + KCHUNK <= SIGCH) {
        for (int idx = tid; idx < 2048; idx += 256) {
            int n = idx >> 5, j = idx & 31;
            float4 v = *(const float4*)&W[(size_t)(colg * 64 + n) * SIGCH + kb + j * 4];
            int o = n * LDT + j * 4;
            float e[4] = {v.x, v.y, v.z, v.w};
#pragma unroll
            for (int q = 0; q < 4; q++) {
                __nv_bfloat16 h = __float2bfloat16(e[q]);
                sBh[o + q] = h;
                sBl[o + q] = __float2bfloat16(e[q] - __bfloat162float(h));
            }
        }
    } else {
        for (int idx = tid; idx < 8192; idx += 256) {
            int n = idx >> 7, k = idx & 127;
            int kg = kb + k;
            float v = (kg < SIGCH) ? W[(size_t)(colg * 64 + n) * SIGCH + kg] : 0.0f;
            __nv_bfloat16 h = __float2bfloat16(v);
            sBh[n * LDT + k] = h;
            sBl[n * LDT + k] = __float2bfloat16(v - __bfloat162float(h));
        }
    }
    __syncthreads();

    wmma::fragment<wmma::accumulator, 16, 16, 16, float> acc[2];
#pragma unroll
    for (int i = 0; i < 2; i++) wmma::fill_fragment(acc[i], 0.0f);

#pragma unroll
    for (int ks = 0; ks < 8; ks++) {
        wmma::fragment<wmma::matrix_a, 16, 16, 16, __nv_bfloat16, wmma::row_major> ah, al;
        wmma::load_matrix_sync(ah, sAh + (rs * 16) * LDT + ks * 16, LDT);
        wmma::load_matrix_sync(al, sAl + (rs * 16) * LDT + ks * 16, LDT);
#pragma unroll
        for (int cf = 0; cf < 2; cf++) {
            int nc = chf * 32 + cf * 16;
            // B tile is [n][k]; col_major fragment reads (k, n) at ptr[k + n*LDT].
            wmma::fragment<wmma::matrix_b, 16, 16, 16, __nv_bfloat16, wmma::col_major> bh, bl;
            wmma::load_matrix_sync(bh, sBh + nc * LDT + ks * 16, LDT);
            wmma::load_matrix_sync(bl, sBl + nc * LDT + ks * 16, LDT);
            wmma::mma_sync(acc[cf], ah, bh, acc[cf]);
            wmma::mma_sync(acc[cf], ah, bl, acc[cf]);
            wmma::mma_sync(acc[cf], al, bh, acc[cf]);
        }
    }

    // Epilogue: fragments -> smem scratch (tiles dead) -> atomicAdd into out.
    __syncthreads();
    float* sc = (float*)ts;                 // 64 x 64 fp32 = 16 KB
#pragma unroll
    for (int cf = 0; cf < 2; cf++)
        wmma::store_matrix_sync(sc + (rs * 16) * 64 + chf * 32 + cf * 16,
                                acc[cf], 64, wmma::mem_row_major);
    __syncthreads();

    for (int e = tid; e < 4096; e += 256) {
        int rr = e >> 6;
        int cc = e & 63;
        atomicAdd(&out[(rowg * 64 + rr) * DOUT + colg * 64 + cc], sc[e]);
    }
}

// ---------------------------------------------------------------------------
extern "C" void kernel_launch(void* const* d_in, const int* in_sizes, int n_in,
                              void* d_out, int out_size)
{
    (void)in_sizes; (void)n_in; (void)out_size;
    const float* inp  = (const float*)d_in[0];   // (128,1024,7)
    const float* W    = (const float*)d_in[1];   // (256,4680)
    const float* bias = (const float*)d_in[2];   // (256,)
    float* out = (float*)d_out;                  // (128,256)

    const int smem_bytes = SMEM_FLOATS * sizeof(float);   // 149760
    cudaFuncSetAttribute(sig_scan_kernel,
                         cudaFuncAttributeMaxDynamicSharedMemorySize, smem_bytes);
    cudaFuncSetAttribute(mma_kernel,
                         cudaFuncAttributeMaxDynamicSharedMemorySize, MMA_SMEM);

    sig_scan_kernel<<<NB, 512, smem_bytes>>>(inp, bias, out);
    dim3 g2(4, 2, KSPLIT);
    mma_kernel<<<g2, 256, MMA_SMEM>>>(W, out);
}